// round 3
// baseline (speedup 1.0000x reference)
#include <cuda_runtime.h>

#define NN 2048
#define OUTC 16

// ---- scratch (device globals; no allocation allowed) ----
__device__ float g_rowsum[NN];
__device__ float g_colsum[NN];
__device__ float g_diag[NN];
__device__ float g_scal[2];           // [0]=trace, [1]=totsum
__device__ float g_Rf[NN * OUTC];     // per-i vector (includes trace/totsum const terms)
__device__ float g_Cc[NN * OUTC];     // per-j vector
__device__ float g_Dd[NN * OUTC];     // diagonal extra terms

// ---------------------------------------------------------------------------
__global__ void k_zero() {
    int t = blockIdx.x * blockDim.x + threadIdx.x;   // 4096 threads
    if (t < NN) g_rowsum[t] = 0.f;
    else        g_colsum[t - NN] = 0.f;
}

// 64x64 tile per block, 256 threads. Coalesced reads; shuffle row-reduce;
// shared then global atomics.
__global__ void k_reduce(const float* __restrict__ A) {
    __shared__ float srow[64];
    __shared__ float scol[64];
    int t = threadIdx.x;
    if (t < 64) { srow[t] = 0.f; scol[t] = 0.f; }
    __syncthreads();
    int i0 = blockIdx.y * 64, j0 = blockIdx.x * 64;
    int lane = t & 31, w = t >> 5;
    float ca0 = 0.f, ca1 = 0.f;
    for (int k = w; k < 128; k += 8) {          // 128 chunks of 32 elements
        int r  = k >> 1;
        int cb = (k & 1) << 5;
        float v = A[(size_t)(i0 + r) * NN + j0 + cb + lane];
        float s = v;
        #pragma unroll
        for (int off = 16; off; off >>= 1) s += __shfl_xor_sync(0xffffffffu, s, off);
        if (lane == 0) atomicAdd(&srow[r], s);
        if (k & 1) ca1 += v; else ca0 += v;
    }
    atomicAdd(&scol[lane], ca0);
    atomicAdd(&scol[32 + lane], ca1);
    __syncthreads();
    if (t < 64) {
        atomicAdd(&g_rowsum[i0 + t], srow[t]);
        atomicAdd(&g_colsum[j0 + t], scol[t]);
    }
}

// 1 block, 1024 threads: diag, trace, totsum
__global__ void k_scal(const float* __restrict__ A) {
    int t = threadIdx.x;
    float d0 = A[(size_t)t * NN + t];
    float d1 = A[(size_t)(t + 1024) * NN + (t + 1024)];
    g_diag[t] = d0;
    g_diag[t + 1024] = d1;
    float tr = d0 + d1;
    float ts = g_rowsum[t] + g_rowsum[t + 1024];
    __shared__ float shtr[32], shts[32];
    int lane = t & 31, w = t >> 5;
    #pragma unroll
    for (int off = 16; off; off >>= 1) {
        tr += __shfl_xor_sync(0xffffffffu, tr, off);
        ts += __shfl_xor_sync(0xffffffffu, ts, off);
    }
    if (lane == 0) { shtr[w] = tr; shts[w] = ts; }
    __syncthreads();
    if (w == 0) {
        tr = shtr[lane];
        ts = shts[lane];
        #pragma unroll
        for (int off = 16; off; off >>= 1) {
            tr += __shfl_xor_sync(0xffffffffu, tr, off);
            ts += __shfl_xor_sync(0xffffffffu, ts, off);
        }
        if (lane == 0) { g_scal[0] = tr; g_scal[1] = ts; }
    }
}

// per-row/col 16-vectors.  w layout: w[k*16 + o], k = 0..14
__global__ void k_pre(const float* __restrict__ w) {
    int i = blockIdx.x * 256 + threadIdx.x;
    float di = g_diag[i], ri = g_rowsum[i], ci = g_colsum[i];
    float tr = g_scal[0], ts = g_scal[1];
    #pragma unroll
    for (int o = 0; o < OUTC; o++) {
        g_Rf[i * OUTC + o] = fmaf(di, w[8*16+o], fmaf(ri, w[9*16+o],
                             fmaf(ci, w[10*16+o], fmaf(tr, w[13*16+o], ts * w[14*16+o]))));
        g_Cc[i * OUTC + o] = fmaf(di, w[5*16+o], fmaf(ri, w[6*16+o], ci * w[7*16+o]));
        g_Dd[i * OUTC + o] = fmaf(di, w[0*16+o], fmaf(ri, w[1*16+o],
                             fmaf(ci, w[2*16+o], fmaf(tr, w[3*16+o], ts * w[4*16+o]))));
    }
}

__device__ __forceinline__ float4 f4add(float4 a, float4 b) {
    return make_float4(a.x + b.x, a.y + b.y, a.z + b.z, a.w + b.w);
}
__device__ __forceinline__ float4 f4fma(float s, float4 w, float4 acc) {
    return make_float4(fmaf(s, w.x, acc.x), fmaf(s, w.y, acc.y),
                       fmaf(s, w.z, acc.z), fmaf(s, w.w, acc.w));
}

// 32x32 output tile per block. A^T via padded smem tile; A direct coalesced.
__global__ __launch_bounds__(256) void k_main(const float* __restrict__ A,
                                              const float* __restrict__ W,
                                              float* __restrict__ out) {
    __shared__ float sB[32][33];
    int t = threadIdx.x;
    int j0 = blockIdx.x * 32, i0 = blockIdx.y * 32;

    // transposed-source tile: rows j0..j0+31, cols i0..i0+31 (coalesced)
    #pragma unroll
    for (int k = 0; k < 4; k++) {
        int e = t + 256 * k;
        int r = e >> 5, c = e & 31;
        sB[r][c] = A[(size_t)(j0 + r) * NN + i0 + c];
    }
    __syncthreads();

    int jj = t & 31, wi = t >> 5;
    int j = j0 + jj;

    const float4* Cc4 = (const float4*)(g_Cc + (size_t)j * OUTC);
    float4 c0 = Cc4[0], c1 = Cc4[1], c2 = Cc4[2], c3 = Cc4[3];
    const float4* w11 = (const float4*)(W + 11 * 16);
    const float4* w12 = (const float4*)(W + 12 * 16);
    float4 b0 = w11[0], b1 = w11[1], b2 = w11[2], b3 = w11[3];
    float4 a0 = w12[0], a1 = w12[1], a2 = w12[2], a3 = w12[3];

    #pragma unroll
    for (int k = 0; k < 4; k++) {
        int ii = wi * 4 + k;
        int i  = i0 + ii;
        float av = A[(size_t)i * NN + j];      // coalesced across lanes
        float tv = sB[jj][ii];                 // A[j][i], conflict-free (stride 33)

        const float4* Rf4 = (const float4*)(g_Rf + (size_t)i * OUTC);
        float4 o0 = f4fma(av, a0, f4fma(tv, b0, f4add(Rf4[0], c0)));
        float4 o1 = f4fma(av, a1, f4fma(tv, b1, f4add(Rf4[1], c1)));
        float4 o2 = f4fma(av, a2, f4fma(tv, b2, f4add(Rf4[2], c2)));
        float4 o3 = f4fma(av, a3, f4fma(tv, b3, f4add(Rf4[3], c3)));

        if (i == j) {   // diagonal extras (only diagonal blocks diverge)
            const float4* Dd4 = (const float4*)(g_Dd + (size_t)i * OUTC);
            o0 = f4add(o0, Dd4[0]);
            o1 = f4add(o1, Dd4[1]);
            o2 = f4add(o2, Dd4[2]);
            o3 = f4add(o3, Dd4[3]);
        }

        float4* op = (float4*)(out + ((size_t)i * NN + j) * OUTC);
        op[0] = o0; op[1] = o1; op[2] = o2; op[3] = o3;
    }
}

extern "C" void kernel_launch(void* const* d_in, const int* in_sizes, int n_in,
                              void* d_out, int out_size) {
    const float* A = (const float*)d_in[0];
    const float* W = (const float*)d_in[1];
    float* out = (float*)d_out;

    k_zero<<<16, 256>>>();
    k_reduce<<<dim3(32, 32), 256>>>(A);
    k_scal<<<1, 1024>>>(A);
    k_pre<<<8, 256>>>(W);
    k_main<<<dim3(64, 64), 256>>>(A, W, out);
}